// round 12
// baseline (speedup 1.0000x reference)
#include <cuda_runtime.h>
#include <cuda_fp16.h>
#include <cstdint>
#include <math.h>

#define EPS 1e-5f

constexpr int Bn = 256, CT = 256, CR = 192, CG = 64;
constexpr int H = 19, W = 19, HW = 361;
constexpr int PY = 21, PX = 24, PP = PY * PX;

constexpr int NK1 = 72;   // 2304/32 K-chunks
constexpr int NK2 = 54;   // 1728/32

constexpr int NTILE = 96;                        // pixels per CTA
constexpr int ASTH = 40, ABUFH = 128 * ASTH;     // 5120 halves
constexpr int BSTH = 40, BBUFH = NTILE * BSTH;   // 3840 halves
constexpr int BUFH = ABUFH + BBUFH;              // 8960 halves/stage
constexpr int SMEMSZ = 2 * BUFH * 2;             // 35840 B dynamic

// ---- device scratch ----
__device__ __half g_act1p[Bn * CT * PP];
__device__ __half g_act2p[Bn * CR * PP];
__device__ float  g_reg [Bn * CR * HW];
__device__ float  g_gp  [Bn * CG * HW];
__device__ float  g_gpo [Bn * CR];
__device__ __half g_wA1 [2 * NK1 * 4096];
__device__ __half g_wA2 [2 * NK2 * 4096];
__device__ int    g_ofs [NK1 * 32];

__device__ __forceinline__ float mishf(float x) {
    if (x > 20.f) return x;
    float t = __expf(x);
    float u = fmaf(t, t, 2.f * t);
    return x * __fdividef(u, u + 2.f);
}
__device__ __forceinline__ void mma_f16(float* d, const uint32_t* a, const uint32_t* b) {
    asm volatile(
        "mma.sync.aligned.m16n8k16.row.col.f32.f16.f16.f32 "
        "{%0,%1,%2,%3}, {%4,%5,%6,%7}, {%8,%9}, {%0,%1,%2,%3};"
        : "+f"(d[0]), "+f"(d[1]), "+f"(d[2]), "+f"(d[3])
        : "r"(a[0]), "r"(a[1]), "r"(a[2]), "r"(a[3]), "r"(b[0]), "r"(b[1]));
}
__device__ __forceinline__ uint32_t smem_u32(const void* p) {
    uint32_t a;
    asm("{ .reg .u64 t; cvta.to.shared.u64 t, %1; cvt.u32.u64 %0, t; }" : "=r"(a) : "l"(p));
    return a;
}
__device__ __forceinline__ void ldmx4(uint32_t* r, uint32_t addr) {
    asm volatile("ldmatrix.sync.aligned.m8n8.x4.shared.b16 {%0,%1,%2,%3}, [%4];"
                 : "=r"(r[0]), "=r"(r[1]), "=r"(r[2]), "=r"(r[3]) : "r"(addr));
}
__device__ __forceinline__ void ldmx2(uint32_t* r, uint32_t addr) {
    asm volatile("ldmatrix.sync.aligned.m8n8.x2.shared.b16 {%0,%1}, [%2];"
                 : "=r"(r[0]), "=r"(r[1]) : "r"(addr));
}
__device__ __forceinline__ void cpa16(uint32_t dst, const void* src) {
    asm volatile("cp.async.cg.shared.global [%0], [%1], 16;" :: "r"(dst), "l"(src));
}
#define CP_COMMIT() asm volatile("cp.async.commit_group;" ::: "memory")
#define CP_WAIT0()  asm volatile("cp.async.wait_group 0;" ::: "memory")

// ---- weight prep ----
__global__ void k_wA1(const float* __restrict__ w1a, const float* __restrict__ w1b) {
    int i = blockIdx.x * blockDim.x + threadIdx.x;
    if (i < NK1 * 32) {
        int ci = i / 9, r = i - ci * 9;
        g_ofs[i] = ci * PP + (r / 3) * PX + (r % 3) - (PX + 1);
    }
    if (i >= 2 * NK1 * 4096) return;
    int blk = i >> 12, q = i & 4095;
    int mt = blk / NK1, kc = blk % NK1;
    int row = q >> 5, k = q & 31;
    int K = kc * 32 + k, ci = K / 9, r = K - ci * 9;
    int cout = mt * 128 + row;
    float v = (cout < CR) ? w1a[(cout * CT + ci) * 9 + r]
                          : w1b[((cout - CR) * CT + ci) * 9 + r];
    g_wA1[i] = __float2half_rn(v);
}
__global__ void k_wA2(const float* __restrict__ w2) {
    int i = blockIdx.x * blockDim.x + threadIdx.x;
    if (i >= 2 * NK2 * 4096) return;
    int blk = i >> 12, q = i & 4095;
    int mt = blk / NK2, kc = blk % NK2;
    int row = q >> 5, k = q & 31;
    int K = kc * 32 + k, ci = K / 9, r = K - ci * 9;
    int cout = mt * 128 + row;
    g_wA2[i] = __float2half_rn(w2[(cout * CR + ci) * 9 + r]);
}

// ---- act prep ----
__global__ void k_pre(const float* __restrict__ x,
                      const float* __restrict__ g, const float* __restrict__ b,
                      const float* __restrict__ m, const float* __restrict__ v) {
    int bx = blockIdx.x;
    int c = bx % CT;
    float sc = g[c] * rsqrtf(v[c] + EPS);
    float bs = fmaf(-m[c], sc, b[c]);
    const float* xp = x + (size_t)bx * HW;
    __half* op = g_act1p + (size_t)bx * PP;
    for (int i = threadIdx.x; i < PP; i += 128) {
        int y = i / PX, xc = i - y * PX;
        float val = 0.f;
        if (y >= 1 && y <= H && xc >= 1 && xc <= W)
            val = mishf(fmaf(xp[(y - 1) * W + (xc - 1)], sc, bs));
        op[i] = __float2half_rn(val);
    }
}
__global__ void k_mid(const float* __restrict__ g, const float* __restrict__ b,
                      const float* __restrict__ m, const float* __restrict__ v) {
    int bx = blockIdx.x;
    int img = bx / CR, c = bx % CR;
    float sc = g[c] * rsqrtf(v[c] + EPS);
    float bs = fmaf(-m[c], sc, b[c]);
    float gv = g_gpo[img * CR + c];
    const float* rp = g_reg + (size_t)bx * HW;
    __half* op = g_act2p + (size_t)bx * PP;
    for (int i = threadIdx.x; i < PP; i += 128) {
        int y = i / PX, xc = i - y * PX;
        float val = 0.f;
        if (y >= 1 && y <= H && xc >= 1 && xc <= W)
            val = mishf(fmaf(rp[(y - 1) * W + (xc - 1)] + gv, sc, bs));
        op[i] = __float2half_rn(val);
    }
}

// ---- fp16 implicit-GEMM conv: CTA 128x96, 8 warps (2M x 4N), warp tile 64x24 ----
template <int NK, int MODE>
__global__ __launch_bounds__(256, 2)
void k_convtc(const float* __restrict__ bg, const float* __restrict__ bb,
              const float* __restrict__ bm, const float* __restrict__ bv,
              const float* __restrict__ resid, float* __restrict__ outp) {
    extern __shared__ __half smh[];
    __shared__ int sofs[NK * 32];
    constexpr int CIN = NK * 32 / 9;

    const __half* gw  = (MODE == 0) ? g_wA1 : g_wA2;
    const __half* gin = (MODE == 0) ? g_act1p : g_act2p;

    const int tid = threadIdx.x, lane = tid & 31, wid = tid >> 5;
    const int Nt = blockIdx.x, Mt = blockIdx.y, img = blockIdx.z;
    const int wm = wid & 1, wn = wid >> 1;       // 2M x 4N
    const int lq = lane >> 2, lr = lane & 3;

    for (int i = tid; i < NK * 32; i += 256) sofs[i] = g_ofs[i];

    // B gather: thread t<192 handles pixel t>>1, half (t&1)*16 taps
    const int gpix = tid >> 1, ghalf = tid & 1;
    int p = Nt * NTILE + gpix;
    if (p > 360) p = 360;
    const int ctr = (p / 19 + 1) * PX + (p % 19 + 1);
    const __half* actimg = gin + (size_t)img * CIN * PP;
    const int4* gwA4 = (const int4*)(gw) + (size_t)Mt * NK * 512;

    const int amrow = wm * 64 + (lane & 7) + 8 * ((lane >> 3) & 1);
    const int amkof = 8 * (lane >> 4);
    const int bnof = (lane & 7) + 8 * (lane >> 4);       // x4 geometry
    const int bkof = 8 * ((lane >> 3) & 1);
    const int b2nof = lane & 7;                           // x2 geometry (lanes 0-15)
    const int b2kof = 8 * ((lane >> 3) & 1);
    const uint32_t smbase = smem_u32(smh);

    float d[4][3][4];
#pragma unroll
    for (int mt = 0; mt < 4; mt++)
#pragma unroll
        for (int nt = 0; nt < 3; nt++)
#pragma unroll
            for (int e = 0; e < 4; e++) d[mt][nt][e] = 0.f;

    uint32_t bregs[8];

    auto ldgA = [&](int kc, int buf) {
        uint32_t Asa = smbase + (buf * BUFH) * 2;
#pragma unroll
        for (int q = tid; q < 512; q += 256) {
            int row = q >> 2, ko = (q & 3) << 3;
            cpa16(Asa + (row * ASTH + ko) * 2, gwA4 + kc * 512 + q);
        }
    };
    auto ldgB = [&](int kc) {
        const int* of = sofs + kc * 32 + ghalf * 16;
#pragma unroll
        for (int k2 = 0; k2 < 8; k2++) {
            uint32_t lo = *(const uint16_t*)(actimg + of[k2 * 2 + 0] + ctr);
            uint32_t hi = *(const uint16_t*)(actimg + of[k2 * 2 + 1] + ctr);
            bregs[k2] = lo | (hi << 16);
        }
    };
    auto stsB = [&](int buf) {
        uint32_t* brow = (uint32_t*)(smh + buf * BUFH + ABUFH + gpix * BSTH + ghalf * 16);
#pragma unroll
        for (int q = 0; q < 2; q++)
            *(uint4*)(brow + q * 4) =
                make_uint4(bregs[q * 4], bregs[q * 4 + 1], bregs[q * 4 + 2], bregs[q * 4 + 3]);
    };

    __syncthreads();
    ldgA(0, 0); CP_COMMIT();
    if (tid < 192) ldgB(0);
    CP_WAIT0();
    if (tid < 192) stsB(0);
    __syncthreads();

    for (int kc = 0; kc < NK; kc++) {
        const int buf = kc & 1;
        if (kc + 1 < NK) {
            ldgA(kc + 1, buf ^ 1); CP_COMMIT();
            if (tid < 192) ldgB(kc + 1);
        }

        const uint32_t Asa = smbase + (buf * BUFH) * 2;
        const uint32_t Bsa = Asa + ABUFH * 2;

#pragma unroll
        for (int ks = 0; ks < 2; ks++) {
            uint32_t a[4][4], b[3][2];
#pragma unroll
            for (int mt = 0; mt < 4; mt++)
                ldmx4(a[mt], Asa + ((amrow + mt * 16) * ASTH + ks * 16 + amkof) * 2);
            {
                uint32_t r[4];
                ldmx4(r, Bsa + ((wn * 24 + bnof) * BSTH + ks * 16 + bkof) * 2);
                b[0][0] = r[0]; b[0][1] = r[1];
                b[1][0] = r[2]; b[1][1] = r[3];
                uint32_t r2[2];
                ldmx2(r2, Bsa + ((wn * 24 + 16 + b2nof) * BSTH + ks * 16 + b2kof) * 2);
                b[2][0] = r2[0]; b[2][1] = r2[1];
            }
#pragma unroll
            for (int mt = 0; mt < 4; mt++)
#pragma unroll
                for (int nt = 0; nt < 3; nt++)
                    mma_f16(d[mt][nt], a[mt], b[nt]);
        }

        if (kc + 1 < NK) {
            if (tid < 192) stsB(buf ^ 1);
            CP_WAIT0();
        }
        __syncthreads();
    }

    // ---- epilogue ----
#pragma unroll
    for (int mt = 0; mt < 4; mt++) {
#pragma unroll
        for (int e2 = 0; e2 < 2; e2++) {
            int row = wm * 64 + mt * 16 + lq + e2 * 8;
            int cout = Mt * 128 + row;
            float sc = 0.f, bs = 0.f;
            if (MODE == 0 && cout >= CR) {
                int c2 = cout - CR;
                sc = bg[c2] * rsqrtf(bv[c2] + EPS);
                bs = fmaf(-bm[c2], sc, bb[c2]);
            }
#pragma unroll
            for (int nt = 0; nt < 3; nt++) {
#pragma unroll
                for (int e1 = 0; e1 < 2; e1++) {
                    int col = wn * 24 + nt * 8 + 2 * lr + e1;
                    int pp = Nt * NTILE + col;
                    if (pp >= HW) continue;
                    float val = d[mt][nt][e2 * 2 + e1];
                    if (MODE == 0) {
                        if (cout < CR)
                            g_reg[((size_t)img * CR + cout) * HW + pp] = val;
                        else
                            g_gp[((size_t)img * CG + (cout - CR)) * HW + pp] =
                                mishf(fmaf(val, sc, bs));
                    } else {
                        size_t off = ((size_t)img * CT + cout) * HW + pp;
                        outp[off] = val + resid[off];
                    }
                }
            }
        }
    }
}

// ---- gpool + linear ----
__global__ void k_gpool(const float* __restrict__ wlin) {
    int img = blockIdx.x;
    int tid = threadIdx.x, warp = tid / 32, lane = tid % 32;
    __shared__ float pooled[3 * CG];
    for (int c = warp; c < CG; c += 8) {
        const float* p = g_gp + ((size_t)img * CG + c) * HW;
        float s = 0.f, mx = -INFINITY;
        for (int i = lane; i < HW; i += 32) {
            float v = p[i];
            s += v; mx = fmaxf(mx, v);
        }
#pragma unroll
        for (int off = 16; off; off >>= 1) {
            s += __shfl_down_sync(0xFFFFFFFFu, s, off);
            mx = fmaxf(mx, __shfl_down_sync(0xFFFFFFFFu, mx, off));
        }
        if (lane == 0) {
            float mean = s * (1.f / 361.f);
            pooled[c] = mean;
            pooled[CG + c] = mean * 0.5f;
            pooled[2 * CG + c] = mx;
        }
    }
    __syncthreads();
    if (tid < CR) {
        float s = 0.f;
        const float* wr = wlin + tid * (3 * CG);
#pragma unroll 4
        for (int k = 0; k < 3 * CG; k++) s = fmaf(pooled[k], wr[k], s);
        g_gpo[img * CR + tid] = s;
    }
}

extern "C" void kernel_launch(void* const* d_in, const int* in_sizes, int n_in,
                              void* d_out, int out_size) {
    const float* x    = (const float*)d_in[0];
    const float* b1g  = (const float*)d_in[1];
    const float* b1b  = (const float*)d_in[2];
    const float* b1m  = (const float*)d_in[3];
    const float* b1v  = (const float*)d_in[4];
    const float* w1a  = (const float*)d_in[5];
    const float* w1b  = (const float*)d_in[6];
    const float* bgg  = (const float*)d_in[7];
    const float* bgb  = (const float*)d_in[8];
    const float* bgm  = (const float*)d_in[9];
    const float* bgv  = (const float*)d_in[10];
    const float* wlin = (const float*)d_in[11];
    const float* b2g  = (const float*)d_in[12];
    const float* b2b  = (const float*)d_in[13];
    const float* b2m  = (const float*)d_in[14];
    const float* b2v  = (const float*)d_in[15];
    const float* w2   = (const float*)d_in[16];
    float* out = (float*)d_out;

    cudaFuncSetAttribute(k_convtc<NK1, 0>, cudaFuncAttributeMaxDynamicSharedMemorySize, SMEMSZ);
    cudaFuncSetAttribute(k_convtc<NK2, 1>, cudaFuncAttributeMaxDynamicSharedMemorySize, SMEMSZ);

    k_wA1<<<(2 * NK1 * 4096 + 255) / 256, 256>>>(w1a, w1b);
    k_wA2<<<(2 * NK2 * 4096 + 255) / 256, 256>>>(w2);
    k_pre<<<Bn * CT, 128>>>(x, b1g, b1b, b1m, b1v);

    dim3 gconv(4, 2, Bn);
    k_convtc<NK1, 0><<<gconv, 256, SMEMSZ>>>(bgg, bgb, bgm, bgv, nullptr, nullptr);
    k_gpool<<<Bn, 256>>>(wlin);
    k_mid<<<Bn * CR, 128>>>(b2g, b2b, b2m, b2v);
    k_convtc<NK2, 1><<<gconv, 256, SMEMSZ>>>(nullptr, nullptr, nullptr, nullptr, x, out);
}

// round 14
// speedup vs baseline: 1.1114x; 1.1114x over previous
#include <cuda_runtime.h>
#include <cuda_fp16.h>
#include <cstdint>
#include <math.h>

#define EPS 1e-5f

constexpr int Bn = 256, CT = 256, CR = 192, CG = 64;
constexpr int H = 19, W = 19, HW = 361;

constexpr int NK1 = 72;   // 2304/32 K-chunks
constexpr int NK2 = 54;   // 1728/32

constexpr int NTILE = 192;                       // pixels per CTA
constexpr int ASTH = 40, ABUFH = 128 * ASTH;     // 5120 halves
constexpr int BSTH = 40, BBUFH = NTILE * BSTH;   // 7680 halves
constexpr int BUFH = ABUFH + BBUFH;              // 12800 halves/stage
constexpr int NSTAGE = 3;
constexpr int SMEMSZ = NSTAGE * BUFH * 2;        // 76800 B dynamic

// ---- device scratch ----
__device__ float  g_reg [Bn * CR * HW];
__device__ float  g_gp  [Bn * CG * HW];
__device__ float  g_gpo [Bn * CR];
__device__ __half g_wA1 [2 * NK1 * 4096];
__device__ __half g_wA2 [2 * NK2 * 4096];
__device__ __half g_B1 [(size_t)Bn * NK1 * 384 * 32];   // im2col for conv1
__device__ __half g_B2 [(size_t)Bn * NK2 * 384 * 32];   // im2col for conv2

__device__ __forceinline__ float mishf(float x) {
    if (x > 20.f) return x;
    float t = __expf(x);
    float u = fmaf(t, t, 2.f * t);
    return x * __fdividef(u, u + 2.f);
}
__device__ __forceinline__ void mma_f16(float* d, const uint32_t* a, const uint32_t* b) {
    asm volatile(
        "mma.sync.aligned.m16n8k16.row.col.f32.f16.f16.f32 "
        "{%0,%1,%2,%3}, {%4,%5,%6,%7}, {%8,%9}, {%0,%1,%2,%3};"
        : "+f"(d[0]), "+f"(d[1]), "+f"(d[2]), "+f"(d[3])
        : "r"(a[0]), "r"(a[1]), "r"(a[2]), "r"(a[3]), "r"(b[0]), "r"(b[1]));
}
__device__ __forceinline__ uint32_t smem_u32(const void* p) {
    uint32_t a;
    asm("{ .reg .u64 t; cvta.to.shared.u64 t, %1; cvt.u32.u64 %0, t; }" : "=r"(a) : "l"(p));
    return a;
}
__device__ __forceinline__ void ldmx4(uint32_t* r, uint32_t addr) {
    asm volatile("ldmatrix.sync.aligned.m8n8.x4.shared.b16 {%0,%1,%2,%3}, [%4];"
                 : "=r"(r[0]), "=r"(r[1]), "=r"(r[2]), "=r"(r[3]) : "r"(addr));
}
__device__ __forceinline__ void cpa16(uint32_t dst, const void* src) {
    asm volatile("cp.async.cg.shared.global [%0], [%1], 16;" :: "r"(dst), "l"(src));
}
#define CP_COMMIT() asm volatile("cp.async.commit_group;" ::: "memory")
#define CP_WAIT0()  asm volatile("cp.async.wait_group 0;" ::: "memory")
#define CP_WAIT1()  asm volatile("cp.async.wait_group 1;" ::: "memory")

// ---- weight prep ----
__global__ void k_wA1(const float* __restrict__ w1a, const float* __restrict__ w1b) {
    int i = blockIdx.x * blockDim.x + threadIdx.x;
    if (i >= 2 * NK1 * 4096) return;
    int blk = i >> 12, q = i & 4095;
    int mt = blk / NK1, kc = blk % NK1;
    int row = q >> 5, k = q & 31;
    int K = kc * 32 + k, ci = K / 9, r = K - ci * 9;
    int cout = mt * 128 + row;
    float v = (cout < CR) ? w1a[(cout * CT + ci) * 9 + r]
                          : w1b[((cout - CR) * CT + ci) * 9 + r];
    g_wA1[i] = __float2half_rn(v);
}
__global__ void k_wA2(const float* __restrict__ w2) {
    int i = blockIdx.x * blockDim.x + threadIdx.x;
    if (i >= 2 * NK2 * 4096) return;
    int blk = i >> 12, q = i & 4095;
    int mt = blk / NK2, kc = blk % NK2;
    int row = q >> 5, k = q & 31;
    int K = kc * 32 + k, ci = K / 9, r = K - ci * 9;
    int cout = mt * 128 + row;
    g_wA2[i] = __float2half_rn(w2[(cout * CR + ci) * 9 + r]);
}

// ---- fused BN+mish+im2col builders ----
// Block = (kc, img). MODE 0: src = x (kernel arg). MODE 1: src = g_reg
// (device-context reference — NEVER passed from host!), bias folds gpool.
template <int CIN, int NK, int MODE>
__global__ __launch_bounds__(256)
void k_im2col(const float* __restrict__ xarg,
              const float* __restrict__ bg, const float* __restrict__ bb,
              const float* __restrict__ bm, const float* __restrict__ bv) {
    __shared__ __half sp[5 * 504];
    __shared__ float ssc[5], sbs[5];
    const int kc = blockIdx.x, img = blockIdx.y;
    const int tid = threadIdx.x;
    const int ci0 = (kc * 32) / 9;
    const int ci1 = (kc * 32 + 31) / 9;
    const int nch = ci1 - ci0 + 1;          // 4 or 5

    const float* src = (MODE == 0) ? xarg : (const float*)g_reg;

    if (tid < nch) {
        int c = ci0 + tid;
        float sc = bg[c] * rsqrtf(bv[c] + EPS);
        float bs = fmaf(-bm[c], sc, bb[c]);
        if (MODE == 1) bs = fmaf(g_gpo[img * CR + c], sc, bs);  // fold gpool bias
        ssc[tid] = sc; sbs[tid] = bs;
    }
    __syncthreads();

    const float* inb = src + ((size_t)img * CIN + ci0) * HW;
    for (int i = tid; i < nch * 504; i += 256) {
        int c = i / 504, q = i - c * 504;
        int y = q / 24, xc = q - y * 24;
        float val = 0.f;
        if (y >= 1 && y <= H && xc >= 1 && xc <= W)
            val = mishf(fmaf(inb[c * HW + (y - 1) * W + (xc - 1)], ssc[c], sbs[c]));
        sp[i] = __float2half_rn(val);
    }
    __syncthreads();

    const int jq = tid & 3;
    int toff[8];
#pragma unroll
    for (int j = 0; j < 8; j++) {
        int kk = kc * 32 + jq * 8 + j;
        int ci = kk / 9, r = kk - ci * 9;
        toff[j] = (ci - ci0) * 504 + (r / 3) * 24 + (r % 3) - 25;
    }
    __half* dst = (MODE == 0 ? g_B1 : g_B2) + ((size_t)(img * NK + kc) * 384) * 32;
#pragma unroll 1
    for (int it = 0; it < 6; it++) {
        int p = it * 64 + (tid >> 2);
        int pc = p > 360 ? 360 : p;
        int ctr = (pc / 19 + 1) * 24 + (pc % 19 + 1);
        uint32_t r4[4];
#pragma unroll
        for (int j2 = 0; j2 < 4; j2++) {
            uint32_t lo = __half_as_ushort(sp[toff[2 * j2] + ctr]);
            uint32_t hi = __half_as_ushort(sp[toff[2 * j2 + 1] + ctr]);
            r4[j2] = lo | (hi << 16);
        }
        *(uint4*)(dst + (size_t)p * 32 + jq * 8) = make_uint4(r4[0], r4[1], r4[2], r4[3]);
    }
}

// ---- fp16 implicit-GEMM conv: CTA 128x192, 8 warps (2M x 4N), warp tile 64x48 ----
// 3-stage cp.async pipeline; B comes pre-im2col'ed from gmem (no gather).
template <int NK, int MODE>
__global__ __launch_bounds__(256)
void k_convtc(const float* __restrict__ bg, const float* __restrict__ bb,
              const float* __restrict__ bm, const float* __restrict__ bv,
              const float* __restrict__ resid, float* __restrict__ outp) {
    extern __shared__ __half smh[];

    const __half* gw = (MODE == 0) ? g_wA1 : g_wA2;
    const __half* gB = (MODE == 0) ? g_B1 : g_B2;

    const int tid = threadIdx.x, lane = tid & 31, wid = tid >> 5;
    const int Nt = blockIdx.x, Mt = blockIdx.y, img = blockIdx.z;
    const int wm = wid & 1, wn = wid >> 1;       // 2M x 4N
    const int lq = lane >> 2, lr = lane & 3;

    const int4* gwA4 = (const int4*)(gw) + (size_t)Mt * NK * 512;
    const __half* gBimg = gB + ((size_t)img * NK) * 384 * 32 + Nt * NTILE * 32;

    const int amrow = wm * 64 + (lane & 7) + 8 * ((lane >> 3) & 1);
    const int amkof = 8 * (lane >> 4);
    const int bnof = (lane & 7) + 8 * (lane >> 4);
    const int bkof = 8 * ((lane >> 3) & 1);
    const uint32_t smbase = smem_u32(smh);

    float d[4][6][4];
#pragma unroll
    for (int mt = 0; mt < 4; mt++)
#pragma unroll
        for (int nt = 0; nt < 6; nt++)
#pragma unroll
            for (int e = 0; e < 4; e++) d[mt][nt][e] = 0.f;

    auto stage = [&](int kc) {
        const int buf = kc % NSTAGE;
        uint32_t Asa = smbase + (buf * BUFH) * 2;
        uint32_t Bsa = Asa + ABUFH * 2;
#pragma unroll
        for (int q = tid; q < 512; q += 256) {
            int row = q >> 2, ko = (q & 3) << 3;
            cpa16(Asa + (row * ASTH + ko) * 2, gwA4 + (size_t)kc * 512 + q);
        }
        const __half* Bsrc = gBimg + (size_t)kc * 384 * 32;
#pragma unroll
        for (int i = 0; i < 3; i++) {
            int q = tid + i * 256;
            int pix = q >> 2, jq = q & 3;
            cpa16(Bsa + (pix * BSTH + jq * 8) * 2, Bsrc + pix * 32 + jq * 8);
        }
        CP_COMMIT();
    };

    stage(0);
    stage(1);

    for (int kc = 0; kc < NK; kc++) {
        if (kc + 2 < NK) CP_WAIT1(); else CP_WAIT0();
        __syncthreads();
        if (kc + 2 < NK) stage(kc + 2);

        const int buf = kc % NSTAGE;
        const uint32_t Asa = smbase + (buf * BUFH) * 2;
        const uint32_t Bsa = Asa + ABUFH * 2;

#pragma unroll
        for (int ks = 0; ks < 2; ks++) {
            uint32_t a[4][4], b[6][2];
#pragma unroll
            for (int mt = 0; mt < 4; mt++)
                ldmx4(a[mt], Asa + ((amrow + mt * 16) * ASTH + ks * 16 + amkof) * 2);
#pragma unroll
            for (int j = 0; j < 3; j++) {
                uint32_t r[4];
                ldmx4(r, Bsa + ((wn * 48 + 16 * j + bnof) * BSTH + ks * 16 + bkof) * 2);
                b[2 * j][0] = r[0]; b[2 * j][1] = r[1];
                b[2 * j + 1][0] = r[2]; b[2 * j + 1][1] = r[3];
            }
#pragma unroll
            for (int mt = 0; mt < 4; mt++)
#pragma unroll
                for (int nt = 0; nt < 6; nt++)
                    mma_f16(d[mt][nt], a[mt], b[nt]);
        }
        __syncthreads();
    }

    // ---- epilogue ----
#pragma unroll
    for (int mt = 0; mt < 4; mt++) {
#pragma unroll
        for (int e2 = 0; e2 < 2; e2++) {
            int row = wm * 64 + mt * 16 + lq + e2 * 8;
            int cout = Mt * 128 + row;
            float sc = 0.f, bs = 0.f;
            if (MODE == 0 && cout >= CR) {
                int c2 = cout - CR;
                sc = bg[c2] * rsqrtf(bv[c2] + EPS);
                bs = fmaf(-bm[c2], sc, bb[c2]);
            }
#pragma unroll
            for (int nt = 0; nt < 6; nt++) {
#pragma unroll
                for (int e1 = 0; e1 < 2; e1++) {
                    int col = wn * 48 + nt * 8 + 2 * lr + e1;
                    int pp = Nt * NTILE + col;
                    if (pp >= HW) continue;
                    float val = d[mt][nt][e2 * 2 + e1];
                    if (MODE == 0) {
                        if (cout < CR)
                            g_reg[((size_t)img * CR + cout) * HW + pp] = val;
                        else
                            g_gp[((size_t)img * CG + (cout - CR)) * HW + pp] =
                                mishf(fmaf(val, sc, bs));
                    } else {
                        size_t off = ((size_t)img * CT + cout) * HW + pp;
                        outp[off] = val + resid[off];
                    }
                }
            }
        }
    }
}

// ---- gpool + linear ----
__global__ void k_gpool(const float* __restrict__ wlin) {
    int img = blockIdx.x;
    int tid = threadIdx.x, warp = tid / 32, lane = tid % 32;
    __shared__ float pooled[3 * CG];
    for (int c = warp; c < CG; c += 8) {
        const float* p = g_gp + ((size_t)img * CG + c) * HW;
        float s = 0.f, mx = -INFINITY;
        for (int i = lane; i < HW; i += 32) {
            float v = p[i];
            s += v; mx = fmaxf(mx, v);
        }
#pragma unroll
        for (int off = 16; off; off >>= 1) {
            s += __shfl_down_sync(0xFFFFFFFFu, s, off);
            mx = fmaxf(mx, __shfl_down_sync(0xFFFFFFFFu, mx, off));
        }
        if (lane == 0) {
            float mean = s * (1.f / 361.f);
            pooled[c] = mean;
            pooled[CG + c] = mean * 0.5f;
            pooled[2 * CG + c] = mx;
        }
    }
    __syncthreads();
    if (tid < CR) {
        float s = 0.f;
        const float* wr = wlin + tid * (3 * CG);
#pragma unroll 4
        for (int k = 0; k < 3 * CG; k++) s = fmaf(pooled[k], wr[k], s);
        g_gpo[img * CR + tid] = s;
    }
}

extern "C" void kernel_launch(void* const* d_in, const int* in_sizes, int n_in,
                              void* d_out, int out_size) {
    const float* x    = (const float*)d_in[0];
    const float* b1g  = (const float*)d_in[1];
    const float* b1b  = (const float*)d_in[2];
    const float* b1m  = (const float*)d_in[3];
    const float* b1v  = (const float*)d_in[4];
    const float* w1a  = (const float*)d_in[5];
    const float* w1b  = (const float*)d_in[6];
    const float* bgg  = (const float*)d_in[7];
    const float* bgb  = (const float*)d_in[8];
    const float* bgm  = (const float*)d_in[9];
    const float* bgv  = (const float*)d_in[10];
    const float* wlin = (const float*)d_in[11];
    const float* b2g  = (const float*)d_in[12];
    const float* b2b  = (const float*)d_in[13];
    const float* b2m  = (const float*)d_in[14];
    const float* b2v  = (const float*)d_in[15];
    const float* w2   = (const float*)d_in[16];
    float* out = (float*)d_out;

    cudaFuncSetAttribute(k_convtc<NK1, 0>, cudaFuncAttributeMaxDynamicSharedMemorySize, SMEMSZ);
    cudaFuncSetAttribute(k_convtc<NK2, 1>, cudaFuncAttributeMaxDynamicSharedMemorySize, SMEMSZ);

    k_wA1<<<(2 * NK1 * 4096 + 255) / 256, 256>>>(w1a, w1b);
    k_wA2<<<(2 * NK2 * 4096 + 255) / 256, 256>>>(w2);

    // build im2col for conv1 (fused bn1 + mish), then conv1
    k_im2col<CT, NK1, 0><<<dim3(NK1, Bn), 256>>>(x, b1g, b1b, b1m, b1v);
    dim3 gconv(2, 2, Bn);
    k_convtc<NK1, 0><<<gconv, 256, SMEMSZ>>>(bgg, bgb, bgm, bgv, nullptr, nullptr);

    k_gpool<<<Bn, 256>>>(wlin);

    // build im2col for conv2 (fused reg+gpo, bn2 + mish), then conv2
    // (xarg unused in MODE 1 — g_reg referenced in device context)
    k_im2col<CR, NK2, 1><<<dim3(NK2, Bn), 256>>>(nullptr, b2g, b2b, b2m, b2v);
    k_convtc<NK2, 1><<<gconv, 256, SMEMSZ>>>(nullptr, nullptr, nullptr, nullptr, x, out);
}

// round 15
// speedup vs baseline: 2.0282x; 1.8250x over previous
#include <cuda_runtime.h>
#include <cuda_fp16.h>
#include <cstdint>
#include <math.h>

#define EPS 1e-5f

constexpr int Bn = 256, CT = 256, CR = 192, CG = 64;
constexpr int H = 19, W = 19, HW = 361;

constexpr int NKC1 = 36;  // 2304/64 K-chunks
constexpr int NKC2 = 27;  // 1728/64

constexpr int NTILE = 192;                        // pixels per CTA
constexpr int ASTH = 72, ABUFH = 128 * ASTH;      // 9216 halves
constexpr int BSTH = 72, BBUFH = NTILE * BSTH;    // 13824 halves
constexpr int BUFH = ABUFH + BBUFH;               // 23040 halves/stage
constexpr int NSTAGE = 2;
constexpr int SMEMSZ = NSTAGE * BUFH * 2;         // 92160 B dynamic

// ---- device scratch ----
__device__ float  g_reg [Bn * CR * HW];
__device__ float  g_gp  [Bn * CG * HW];
__device__ float  g_gpo [Bn * CR];
__device__ __half g_wA1 [2 * NKC1 * 8192];        // [mt][kc64][row128][k64]
__device__ __half g_wA2 [2 * NKC2 * 8192];
__device__ __half g_B1 [(size_t)Bn * NKC1 * 384 * 64];  // im2col conv1
__device__ __half g_B2 [(size_t)Bn * NKC2 * 384 * 64];  // im2col conv2

__device__ __forceinline__ float mishf(float x) {
    if (x > 20.f) return x;
    float t = __expf(x);
    float u = fmaf(t, t, 2.f * t);
    return x * __fdividef(u, u + 2.f);
}
__device__ __forceinline__ void mma_f16(float* d, const uint32_t* a, const uint32_t* b) {
    asm volatile(
        "mma.sync.aligned.m16n8k16.row.col.f32.f16.f16.f32 "
        "{%0,%1,%2,%3}, {%4,%5,%6,%7}, {%8,%9}, {%0,%1,%2,%3};"
        : "+f"(d[0]), "+f"(d[1]), "+f"(d[2]), "+f"(d[3])
        : "r"(a[0]), "r"(a[1]), "r"(a[2]), "r"(a[3]), "r"(b[0]), "r"(b[1]));
}
__device__ __forceinline__ uint32_t smem_u32(const void* p) {
    uint32_t a;
    asm("{ .reg .u64 t; cvta.to.shared.u64 t, %1; cvt.u32.u64 %0, t; }" : "=r"(a) : "l"(p));
    return a;
}
__device__ __forceinline__ void ldmx4(uint32_t* r, uint32_t addr) {
    asm volatile("ldmatrix.sync.aligned.m8n8.x4.shared.b16 {%0,%1,%2,%3}, [%4];"
                 : "=r"(r[0]), "=r"(r[1]), "=r"(r[2]), "=r"(r[3]) : "r"(addr));
}
__device__ __forceinline__ void cpa16(uint32_t dst, const void* src) {
    asm volatile("cp.async.cg.shared.global [%0], [%1], 16;" :: "r"(dst), "l"(src));
}
#define CP_COMMIT() asm volatile("cp.async.commit_group;" ::: "memory")
#define CP_WAIT0()  asm volatile("cp.async.wait_group 0;" ::: "memory")
#define CP_WAIT1()  asm volatile("cp.async.wait_group 1;" ::: "memory")

// ---- weight prep: OIHW -> [mt][kc64][row][k64] fp16 ----
__global__ void k_wA1(const float* __restrict__ w1a, const float* __restrict__ w1b) {
    int i = blockIdx.x * blockDim.x + threadIdx.x;
    if (i >= 2 * NKC1 * 8192) return;
    int blk = i >> 13, q = i & 8191;
    int mt = blk / NKC1, kc = blk % NKC1;
    int row = q >> 6, k = q & 63;
    int K = kc * 64 + k, ci = K / 9, r = K - ci * 9;
    int cout = mt * 128 + row;
    float v = (cout < CR) ? w1a[(cout * CT + ci) * 9 + r]
                          : w1b[((cout - CR) * CT + ci) * 9 + r];
    g_wA1[i] = __float2half_rn(v);
}
__global__ void k_wA2(const float* __restrict__ w2) {
    int i = blockIdx.x * blockDim.x + threadIdx.x;
    if (i >= 2 * NKC2 * 8192) return;
    int blk = i >> 13, q = i & 8191;
    int mt = blk / NKC2, kc = blk % NKC2;
    int row = q >> 6, k = q & 63;
    int K = kc * 64 + k, ci = K / 9, r = K - ci * 9;
    int cout = mt * 128 + row;
    g_wA2[i] = __float2half_rn(w2[(cout * CR + ci) * 9 + r]);
}

// ---- fused BN+mish+im2col builders (64-wide K slices) ----
// Block = (kc64, img). MODE 0: src = x (arg). MODE 1: src = g_reg (device ref!).
template <int CIN, int NKC, int MODE>
__global__ __launch_bounds__(256)
void k_im2col(const float* __restrict__ xarg,
              const float* __restrict__ bg, const float* __restrict__ bb,
              const float* __restrict__ bm, const float* __restrict__ bv) {
    __shared__ __half sp[9 * 504];
    __shared__ float ssc[9], sbs[9];
    const int kc = blockIdx.x, img = blockIdx.y;
    const int tid = threadIdx.x;
    const int ci0 = (kc * 64) / 9;
    const int ci1 = (kc * 64 + 63) / 9;
    const int nch = ci1 - ci0 + 1;          // 8 or 9

    const float* src = (MODE == 0) ? xarg : (const float*)g_reg;

    if (tid < nch) {
        int c = ci0 + tid;
        float sc = bg[c] * rsqrtf(bv[c] + EPS);
        float bs = fmaf(-bm[c], sc, bb[c]);
        if (MODE == 1) bs = fmaf(g_gpo[img * CR + c], sc, bs);  // fold gpool bias
        ssc[tid] = sc; sbs[tid] = bs;
    }
    __syncthreads();

    const float* inb = src + ((size_t)img * CIN + ci0) * HW;
    for (int i = tid; i < nch * 504; i += 256) {
        int c = i / 504, q = i - c * 504;
        int y = q / 24, xc = q - y * 24;
        float val = 0.f;
        if (y >= 1 && y <= H && xc >= 1 && xc <= W)
            val = mishf(fmaf(inb[c * HW + (y - 1) * W + (xc - 1)], ssc[c], sbs[c]));
        sp[i] = __float2half_rn(val);
    }
    __syncthreads();

    const int jq = tid & 7;
    int toff[8];
#pragma unroll
    for (int j = 0; j < 8; j++) {
        int kk = kc * 64 + jq * 8 + j;
        int ci = kk / 9, r = kk - ci * 9;
        toff[j] = (ci - ci0) * 504 + (r / 3) * 24 + (r % 3) - 25;
    }
    __half* dst = (MODE == 0 ? g_B1 : g_B2) + ((size_t)(img * NKC + kc) * 384) * 64;
#pragma unroll 1
    for (int it = 0; it < 12; it++) {
        int p = it * 32 + (tid >> 3);
        int pc = p > 360 ? 360 : p;
        int ctr = (pc / 19 + 1) * 24 + (pc % 19 + 1);
        uint32_t r4[4];
#pragma unroll
        for (int j2 = 0; j2 < 4; j2++) {
            uint32_t lo = __half_as_ushort(sp[toff[2 * j2] + ctr]);
            uint32_t hi = __half_as_ushort(sp[toff[2 * j2 + 1] + ctr]);
            r4[j2] = lo | (hi << 16);
        }
        *(uint4*)(dst + (size_t)p * 64 + jq * 8) = make_uint4(r4[0], r4[1], r4[2], r4[3]);
    }
}

// ---- fp16 implicit-GEMM conv: CTA 128x192, K64 chunks, 2-stage cp.async ----
template <int NKC, int MODE>
__global__ __launch_bounds__(256, 2)
void k_convtc(const float* __restrict__ bg, const float* __restrict__ bb,
              const float* __restrict__ bm, const float* __restrict__ bv,
              const float* __restrict__ resid, float* __restrict__ outp) {
    extern __shared__ __half smh[];

    const __half* gw = (MODE == 0) ? g_wA1 : g_wA2;
    const __half* gB = (MODE == 0) ? g_B1 : g_B2;

    const int tid = threadIdx.x, lane = tid & 31, wid = tid >> 5;
    const int Nt = blockIdx.x, Mt = blockIdx.y, img = blockIdx.z;
    const int wm = wid & 1, wn = wid >> 1;       // 2M x 4N
    const int lq = lane >> 2, lr = lane & 3;

    const int4* gwA4 = (const int4*)(gw) + (size_t)Mt * NKC * 1024;
    const __half* gBimg = gB + ((size_t)img * NKC) * 384 * 64 + Nt * NTILE * 64;

    const int amrow = wm * 64 + (lane & 7) + 8 * ((lane >> 3) & 1);
    const int amkof = 8 * (lane >> 4);
    const int bnof = (lane & 7) + 8 * (lane >> 4);
    const int bkof = 8 * ((lane >> 3) & 1);
    const uint32_t smbase = smem_u32(smh);

    float d[4][6][4];
#pragma unroll
    for (int mt = 0; mt < 4; mt++)
#pragma unroll
        for (int nt = 0; nt < 6; nt++)
#pragma unroll
            for (int e = 0; e < 4; e++) d[mt][nt][e] = 0.f;

    auto stage = [&](int kc) {
        const int buf = kc & 1;
        uint32_t Asa = smbase + (buf * BUFH) * 2;
        uint32_t Bsa = Asa + ABUFH * 2;
#pragma unroll
        for (int i = 0; i < 4; i++) {
            int q = tid + i * 256;                // 1024 int4 of A
            int row = q >> 3, ko = (q & 7) << 3;
            cpa16(Asa + (row * ASTH + ko) * 2, gwA4 + (size_t)kc * 1024 + q);
        }
        const __half* Bsrc = gBimg + (size_t)kc * 384 * 64;
#pragma unroll
        for (int i = 0; i < 6; i++) {
            int q = tid + i * 256;                // 1536 int4 of B
            int pix = q >> 3, jq = q & 7;
            cpa16(Bsa + (pix * BSTH + jq * 8) * 2, Bsrc + pix * 64 + jq * 8);
        }
        CP_COMMIT();
    };

    stage(0);

    for (int kc = 0; kc < NKC; kc++) {
        if (kc + 1 < NKC) { stage(kc + 1); CP_WAIT1(); } else { CP_WAIT0(); }
        __syncthreads();

        const int buf = kc & 1;
        const uint32_t Asa = smbase + (buf * BUFH) * 2;
        const uint32_t Bsa = Asa + ABUFH * 2;

#pragma unroll
        for (int ks = 0; ks < 4; ks++) {
            uint32_t a[4][4], b[6][2];
#pragma unroll
            for (int mt = 0; mt < 4; mt++)
                ldmx4(a[mt], Asa + ((amrow + mt * 16) * ASTH + ks * 16 + amkof) * 2);
#pragma unroll
            for (int j = 0; j < 3; j++) {
                uint32_t r[4];
                ldmx4(r, Bsa + ((wn * 48 + 16 * j + bnof) * BSTH + ks * 16 + bkof) * 2);
                b[2 * j][0] = r[0]; b[2 * j][1] = r[1];
                b[2 * j + 1][0] = r[2]; b[2 * j + 1][1] = r[3];
            }
#pragma unroll
            for (int mt = 0; mt < 4; mt++)
#pragma unroll
                for (int nt = 0; nt < 6; nt++)
                    mma_f16(d[mt][nt], a[mt], b[nt]);
        }
        __syncthreads();
    }

    // ---- epilogue ----
#pragma unroll
    for (int mt = 0; mt < 4; mt++) {
#pragma unroll
        for (int e2 = 0; e2 < 2; e2++) {
            int row = wm * 64 + mt * 16 + lq + e2 * 8;
            int cout = Mt * 128 + row;
            float sc = 0.f, bs = 0.f;
            if (MODE == 0 && cout >= CR) {
                int c2 = cout - CR;
                sc = bg[c2] * rsqrtf(bv[c2] + EPS);
                bs = fmaf(-bm[c2], sc, bb[c2]);
            }
#pragma unroll
            for (int nt = 0; nt < 6; nt++) {
#pragma unroll
                for (int e1 = 0; e1 < 2; e1++) {
                    int col = wn * 48 + nt * 8 + 2 * lr + e1;
                    int pp = Nt * NTILE + col;
                    if (pp >= HW) continue;
                    float val = d[mt][nt][e2 * 2 + e1];
                    if (MODE == 0) {
                        if (cout < CR)
                            g_reg[((size_t)img * CR + cout) * HW + pp] = val;
                        else
                            g_gp[((size_t)img * CG + (cout - CR)) * HW + pp] =
                                mishf(fmaf(val, sc, bs));
                    } else {
                        size_t off = ((size_t)img * CT + cout) * HW + pp;
                        outp[off] = val + resid[off];
                    }
                }
            }
        }
    }
}

// ---- gpool + linear ----
__global__ void k_gpool(const float* __restrict__ wlin) {
    int img = blockIdx.x;
    int tid = threadIdx.x, warp = tid / 32, lane = tid % 32;
    __shared__ float pooled[3 * CG];
    for (int c = warp; c < CG; c += 8) {
        const float* p = g_gp + ((size_t)img * CG + c) * HW;
        float s = 0.f, mx = -INFINITY;
        for (int i = lane; i < HW; i += 32) {
            float v = p[i];
            s += v; mx = fmaxf(mx, v);
        }
#pragma unroll
        for (int off = 16; off; off >>= 1) {
            s += __shfl_down_sync(0xFFFFFFFFu, s, off);
            mx = fmaxf(mx, __shfl_down_sync(0xFFFFFFFFu, mx, off));
        }
        if (lane == 0) {
            float mean = s * (1.f / 361.f);
            pooled[c] = mean;
            pooled[CG + c] = mean * 0.5f;
            pooled[2 * CG + c] = mx;
        }
    }
    __syncthreads();
    if (tid < CR) {
        float s = 0.f;
        const float* wr = wlin + tid * (3 * CG);
#pragma unroll 4
        for (int k = 0; k < 3 * CG; k++) s = fmaf(pooled[k], wr[k], s);
        g_gpo[img * CR + tid] = s;
    }
}

extern "C" void kernel_launch(void* const* d_in, const int* in_sizes, int n_in,
                              void* d_out, int out_size) {
    const float* x    = (const float*)d_in[0];
    const float* b1g  = (const float*)d_in[1];
    const float* b1b  = (const float*)d_in[2];
    const float* b1m  = (const float*)d_in[3];
    const float* b1v  = (const float*)d_in[4];
    const float* w1a  = (const float*)d_in[5];
    const float* w1b  = (const float*)d_in[6];
    const float* bgg  = (const float*)d_in[7];
    const float* bgb  = (const float*)d_in[8];
    const float* bgm  = (const float*)d_in[9];
    const float* bgv  = (const float*)d_in[10];
    const float* wlin = (const float*)d_in[11];
    const float* b2g  = (const float*)d_in[12];
    const float* b2b  = (const float*)d_in[13];
    const float* b2m  = (const float*)d_in[14];
    const float* b2v  = (const float*)d_in[15];
    const float* w2   = (const float*)d_in[16];
    float* out = (float*)d_out;

    cudaFuncSetAttribute(k_convtc<NKC1, 0>, cudaFuncAttributeMaxDynamicSharedMemorySize, SMEMSZ);
    cudaFuncSetAttribute(k_convtc<NKC2, 1>, cudaFuncAttributeMaxDynamicSharedMemorySize, SMEMSZ);

    k_wA1<<<(2 * NKC1 * 8192 + 255) / 256, 256>>>(w1a, w1b);
    k_wA2<<<(2 * NKC2 * 8192 + 255) / 256, 256>>>(w2);

    // build im2col for conv1 (fused bn1 + mish), then conv1
    k_im2col<CT, NKC1, 0><<<dim3(NKC1, Bn), 256>>>(x, b1g, b1b, b1m, b1v);
    dim3 gconv(2, 2, Bn);
    k_convtc<NKC1, 0><<<gconv, 256, SMEMSZ>>>(bgg, bgb, bgm, bgv, nullptr, nullptr);

    k_gpool<<<Bn, 256>>>(wlin);

    // build im2col for conv2 (fused reg+gpo+bn2+mish; g_reg referenced in device code)
    k_im2col<CR, NKC2, 1><<<dim3(NKC2, Bn), 256>>>(nullptr, b2g, b2b, b2m, b2v);
    k_convtc<NKC2, 1><<<gconv, 256, SMEMSZ>>>(nullptr, nullptr, nullptr, nullptr, x, out);
}

// round 16
// speedup vs baseline: 2.2883x; 1.1282x over previous
#include <cuda_runtime.h>
#include <cuda_fp16.h>
#include <cstdint>
#include <math.h>

#define EPS 1e-5f

constexpr int Bn = 256, CT = 256, CR = 192, CG = 64;
constexpr int H = 19, W = 19, HW = 361;
constexpr int PP = 504;   // padded 21x24 pixel plane

constexpr int NCB1 = 4, NKC1 = 9 * NCB1;   // 36 chunks (tap-major)
constexpr int NCB2 = 3, NKC2 = 9 * NCB2;   // 27 chunks

constexpr int NTILE = 192;                        // pixels per CTA
constexpr int ASTH = 72, ABUFH = 128 * ASTH;      // 9216 halves
constexpr int BSTH = 72, BBUFH = NTILE * BSTH;    // 13824 halves
constexpr int BUFH = ABUFH + BBUFH;               // 23040 halves/stage
constexpr int SMEMSZ = 2 * BUFH * 2;              // 92160 B dynamic

// ---- device scratch ----
__device__ float  g_reg [Bn * CR * HW];
__device__ float  g_gp  [Bn * CG * HW];
__device__ float  g_gpo [Bn * CR];
__device__ __half g_wA1 [2 * NKC1 * 8192];        // [mt][kc][row128][k64]
__device__ __half g_wA2 [2 * NKC2 * 8192];
__device__ __half g_h1 [(size_t)Bn * PP * CT];    // NHWC padded act for conv1
__device__ __half g_h2 [(size_t)Bn * PP * CR];    // NHWC padded act for conv2

__device__ __forceinline__ float mishf(float x) {
    if (x > 20.f) return x;
    float t = __expf(x);
    float u = fmaf(t, t, 2.f * t);
    return x * __fdividef(u, u + 2.f);
}
__device__ __forceinline__ void mma_f16(float* d, const uint32_t* a, const uint32_t* b) {
    asm volatile(
        "mma.sync.aligned.m16n8k16.row.col.f32.f16.f16.f32 "
        "{%0,%1,%2,%3}, {%4,%5,%6,%7}, {%8,%9}, {%0,%1,%2,%3};"
        : "+f"(d[0]), "+f"(d[1]), "+f"(d[2]), "+f"(d[3])
        : "r"(a[0]), "r"(a[1]), "r"(a[2]), "r"(a[3]), "r"(b[0]), "r"(b[1]));
}
__device__ __forceinline__ uint32_t smem_u32(const void* p) {
    uint32_t a;
    asm("{ .reg .u64 t; cvta.to.shared.u64 t, %1; cvt.u32.u64 %0, t; }" : "=r"(a) : "l"(p));
    return a;
}
__device__ __forceinline__ void ldmx4(uint32_t* r, uint32_t addr) {
    asm volatile("ldmatrix.sync.aligned.m8n8.x4.shared.b16 {%0,%1,%2,%3}, [%4];"
                 : "=r"(r[0]), "=r"(r[1]), "=r"(r[2]), "=r"(r[3]) : "r"(addr));
}
__device__ __forceinline__ void cpa16(uint32_t dst, const void* src) {
    asm volatile("cp.async.cg.shared.global [%0], [%1], 16;" :: "r"(dst), "l"(src));
}
#define CP_COMMIT() asm volatile("cp.async.commit_group;" ::: "memory")
#define CP_WAIT0()  asm volatile("cp.async.wait_group 0;" ::: "memory")
#define CP_WAIT1()  asm volatile("cp.async.wait_group 1;" ::: "memory")

// ---- zero-fill NHWC buffers (borders stay zero after interior writes) ----
__global__ void k_zero() {
    size_t n1 = (size_t)Bn * PP * CT / 8, n2 = (size_t)Bn * PP * CR / 8;
    size_t i = (size_t)blockIdx.x * blockDim.x + threadIdx.x;
    if (i < n1) ((uint4*)g_h1)[i] = make_uint4(0, 0, 0, 0);
    if (i < n2) ((uint4*)g_h2)[i] = make_uint4(0, 0, 0, 0);
}

// ---- weight prep: OIHW -> [mt][kc=(r,cb)][row][k64] fp16 ----
__global__ void k_wA1(const float* __restrict__ w1a, const float* __restrict__ w1b) {
    int i = blockIdx.x * blockDim.x + threadIdx.x;
    if (i >= 2 * NKC1 * 8192) return;
    int blk = i >> 13, q = i & 8191;
    int mt = blk / NKC1, kc = blk % NKC1;
    int row = q >> 6, k = q & 63;
    int r = kc >> 2, cb = kc & 3;
    int ci = cb * 64 + k;
    int cout = mt * 128 + row;
    float v = (cout < CR) ? w1a[(cout * CT + ci) * 9 + r]
                          : w1b[((cout - CR) * CT + ci) * 9 + r];
    g_wA1[i] = __float2half_rn(v);
}
__global__ void k_wA2(const float* __restrict__ w2) {
    int i = blockIdx.x * blockDim.x + threadIdx.x;
    if (i >= 2 * NKC2 * 8192) return;
    int blk = i >> 13, q = i & 8191;
    int mt = blk / NKC2, kc = blk % NKC2;
    int row = q >> 6, k = q & 63;
    int r = kc / 3, cb = kc - r * 3;
    int ci = cb * 64 + k;
    int cout = mt * 128 + row;
    g_wA2[i] = __float2half_rn(w2[(cout * CR + ci) * 9 + r]);
}

// ---- BN+mish + NCHW->NHWC fp16 transpose (interior pixels only) ----
// Grid (cb, img). MODE 0: src = x arg, dst = g_h1. MODE 1: src = g_reg (+gpo), dst = g_h2.
template <int CIN, int MODE>
__global__ __launch_bounds__(256)
void k_act(const float* __restrict__ xarg,
           const float* __restrict__ bg, const float* __restrict__ bb,
           const float* __restrict__ bm, const float* __restrict__ bv) {
    __shared__ __half sm[361 * 66];
    __shared__ float ssc[64], sbs[64];
    const int cb = blockIdx.x, img = blockIdx.y;
    const int tid = threadIdx.x;

    const float* src = (MODE == 0) ? xarg : (const float*)g_reg;
    __half* dst = (MODE == 0) ? g_h1 : g_h2;

    if (tid < 64) {
        int c = cb * 64 + tid;
        float sc = bg[c] * rsqrtf(bv[c] + EPS);
        float bs = fmaf(-bm[c], sc, bb[c]);
        if (MODE == 1) bs = fmaf(g_gpo[img * CR + c], sc, bs);
        ssc[tid] = sc; sbs[tid] = bs;
    }
    __syncthreads();

    const float* inb = src + ((size_t)img * CIN + cb * 64) * HW;
    for (int i = tid; i < 64 * HW; i += 256) {
        int ci = i / HW, p = i - ci * HW;
        sm[p * 66 + ci] = __float2half_rn(mishf(fmaf(inb[i], ssc[ci], sbs[ci])));
    }
    __syncthreads();

    __half* db = dst + (size_t)img * PP * CIN + cb * 64;
    for (int i = tid; i < HW * 32; i += 256) {
        int p = i >> 5, t = i & 31;
        int ctr = (p / 19 + 1) * 24 + (p % 19) + 1;
        uint32_t lo = __half_as_ushort(sm[p * 66 + 2 * t]);
        uint32_t hi = __half_as_ushort(sm[p * 66 + 2 * t + 1]);
        *(uint32_t*)(db + (size_t)ctr * CIN + 2 * t) = lo | (hi << 16);
    }
}

// ---- fp16 implicit-GEMM conv: CTA 128x192, tap-shifted NHWC B, K64 chunks ----
template <int CIN, int NCB, int MODE>
__global__ __launch_bounds__(256, 2)
void k_convtc(const float* __restrict__ bg, const float* __restrict__ bb,
              const float* __restrict__ bm, const float* __restrict__ bv,
              const float* __restrict__ resid, float* __restrict__ outp) {
    extern __shared__ __half smh[];
    constexpr int NKC = 9 * NCB;

    const __half* gw   = (MODE == 0) ? g_wA1 : g_wA2;
    const __half* gact = (MODE == 0) ? g_h1 : g_h2;

    const int tid = threadIdx.x, lane = tid & 31, wid = tid >> 5;
    const int Nt = blockIdx.x, Mt = blockIdx.y, img = blockIdx.z;
    const int wm = wid & 1, wn = wid >> 1;       // 2M x 4N
    const int lq = lane >> 2, lr = lane & 3;

    const int4* gwA4 = (const int4*)(gw) + (size_t)Mt * NKC * 1024;
    const __half* actimg = gact + (size_t)img * PP * CIN;

    // per-thread B staging geometry: 6 pixel rows, 8 threads per row (jq)
    const int jq = tid & 7;
    int bctr[6];
#pragma unroll
    for (int i = 0; i < 6; i++) {
        int p = Nt * NTILE + (tid >> 3) + 32 * i;
        if (p > 360) p = 360;
        bctr[i] = (p / 19 + 1) * 24 + (p % 19) + 1;
    }

    const int amrow = wm * 64 + (lane & 7) + 8 * ((lane >> 3) & 1);
    const int amkof = 8 * (lane >> 4);
    const int bnof = (lane & 7) + 8 * (lane >> 4);
    const int bkof = 8 * ((lane >> 3) & 1);
    const uint32_t smbase = smem_u32(smh);

    float d[4][6][4];
#pragma unroll
    for (int mt = 0; mt < 4; mt++)
#pragma unroll
        for (int nt = 0; nt < 6; nt++)
#pragma unroll
            for (int e = 0; e < 4; e++) d[mt][nt][e] = 0.f;

    auto stage = [&](int kc) {
        const int buf = kc & 1;
        uint32_t Asa = smbase + (buf * BUFH) * 2;
        uint32_t Bsa = Asa + ABUFH * 2;
#pragma unroll
        for (int i = 0; i < 4; i++) {
            int q = tid + i * 256;                // 1024 int4 of A
            int row = q >> 3, ko = (q & 7) << 3;
            cpa16(Asa + (row * ASTH + ko) * 2, gwA4 + (size_t)kc * 1024 + q);
        }
        const int r = kc / NCB, cb = kc - r * NCB;
        const int off = (r / 3) * 24 + (r % 3) - 25;
        const __half* bsrc = actimg + cb * 64 + jq * 8;
#pragma unroll
        for (int i = 0; i < 6; i++) {
            int pix = (tid >> 3) + 32 * i;
            cpa16(Bsa + (pix * BSTH + jq * 8) * 2,
                  bsrc + (size_t)(bctr[i] + off) * CIN);
        }
        CP_COMMIT();
    };

    stage(0);

    for (int kc = 0; kc < NKC; kc++) {
        if (kc + 1 < NKC) { stage(kc + 1); CP_WAIT1(); } else { CP_WAIT0(); }
        __syncthreads();

        const int buf = kc & 1;
        const uint32_t Asa = smbase + (buf * BUFH) * 2;
        const uint32_t Bsa = Asa + ABUFH * 2;

#pragma unroll
        for (int ks = 0; ks < 4; ks++) {
            uint32_t a[4][4], b[6][2];
#pragma unroll
            for (int mt = 0; mt < 4; mt++)
                ldmx4(a[mt], Asa + ((amrow + mt * 16) * ASTH + ks * 16 + amkof) * 2);
#pragma unroll
            for (int j = 0; j < 3; j++) {
                uint32_t r[4];
                ldmx4(r, Bsa + ((wn * 48 + 16 * j + bnof) * BSTH + ks * 16 + bkof) * 2);
                b[2 * j][0] = r[0]; b[2 * j][1] = r[1];
                b[2 * j + 1][0] = r[2]; b[2 * j + 1][1] = r[3];
            }
#pragma unroll
            for (int mt = 0; mt < 4; mt++)
#pragma unroll
                for (int nt = 0; nt < 6; nt++)
                    mma_f16(d[mt][nt], a[mt], b[nt]);
        }
        __syncthreads();
    }

    // ---- epilogue ----
#pragma unroll
    for (int mt = 0; mt < 4; mt++) {
#pragma unroll
        for (int e2 = 0; e2 < 2; e2++) {
            int row = wm * 64 + mt * 16 + lq + e2 * 8;
            int cout = Mt * 128 + row;
            float sc = 0.f, bs = 0.f;
            if (MODE == 0 && cout >= CR) {
                int c2 = cout - CR;
                sc = bg[c2] * rsqrtf(bv[c2] + EPS);
                bs = fmaf(-bm[c2], sc, bb[c2]);
            }
#pragma unroll
            for (int nt = 0; nt < 6; nt++) {
#pragma unroll
                for (int e1 = 0; e1 < 2; e1++) {
                    int col = wn * 48 + nt * 8 + 2 * lr + e1;
                    int pp = Nt * NTILE + col;
                    if (pp >= HW) continue;
                    float val = d[mt][nt][e2 * 2 + e1];
                    if (MODE == 0) {
                        if (cout < CR)
                            g_reg[((size_t)img * CR + cout) * HW + pp] = val;
                        else
                            g_gp[((size_t)img * CG + (cout - CR)) * HW + pp] =
                                mishf(fmaf(val, sc, bs));
                    } else {
                        size_t off = ((size_t)img * CT + cout) * HW + pp;
                        outp[off] = val + resid[off];
                    }
                }
            }
        }
    }
}

// ---- gpool + linear ----
__global__ void k_gpool(const float* __restrict__ wlin) {
    int img = blockIdx.x;
    int tid = threadIdx.x, warp = tid / 32, lane = tid % 32;
    __shared__ float pooled[3 * CG];
    for (int c = warp; c < CG; c += 8) {
        const float* p = g_gp + ((size_t)img * CG + c) * HW;
        float s = 0.f, mx = -INFINITY;
        for (int i = lane; i < HW; i += 32) {
            float v = p[i];
            s += v; mx = fmaxf(mx, v);
        }
#pragma unroll
        for (int off = 16; off; off >>= 1) {
            s += __shfl_down_sync(0xFFFFFFFFu, s, off);
            mx = fmaxf(mx, __shfl_down_sync(0xFFFFFFFFu, mx, off));
        }
        if (lane == 0) {
            float mean = s * (1.f / 361.f);
            pooled[c] = mean;
            pooled[CG + c] = mean * 0.5f;
            pooled[2 * CG + c] = mx;
        }
    }
    __syncthreads();
    if (tid < CR) {
        float s = 0.f;
        const float* wr = wlin + tid * (3 * CG);
#pragma unroll 4
        for (int k = 0; k < 3 * CG; k++) s = fmaf(pooled[k], wr[k], s);
        g_gpo[img * CR + tid] = s;
    }
}

extern "C" void kernel_launch(void* const* d_in, const int* in_sizes, int n_in,
                              void* d_out, int out_size) {
    const float* x    = (const float*)d_in[0];
    const float* b1g  = (const float*)d_in[1];
    const float* b1b  = (const float*)d_in[2];
    const float* b1m  = (const float*)d_in[3];
    const float* b1v  = (const float*)d_in[4];
    const float* w1a  = (const float*)d_in[5];
    const float* w1b  = (const float*)d_in[6];
    const float* bgg  = (const float*)d_in[7];
    const float* bgb  = (const float*)d_in[8];
    const float* bgm  = (const float*)d_in[9];
    const float* bgv  = (const float*)d_in[10];
    const float* wlin = (const float*)d_in[11];
    const float* b2g  = (const float*)d_in[12];
    const float* b2b  = (const float*)d_in[13];
    const float* b2m  = (const float*)d_in[14];
    const float* b2v  = (const float*)d_in[15];
    const float* w2   = (const float*)d_in[16];
    float* out = (float*)d_out;

    cudaFuncSetAttribute(k_convtc<CT, NCB1, 0>, cudaFuncAttributeMaxDynamicSharedMemorySize, SMEMSZ);
    cudaFuncSetAttribute(k_convtc<CR, NCB2, 1>, cudaFuncAttributeMaxDynamicSharedMemorySize, SMEMSZ);

    size_t nz = (size_t)Bn * PP * CT / 8;
    k_zero<<<(int)((nz + 255) / 256), 256>>>();
    k_wA1<<<(2 * NKC1 * 8192 + 255) / 256, 256>>>(w1a, w1b);
    k_wA2<<<(2 * NKC2 * 8192 + 255) / 256, 256>>>(w2);

    // act1 (bn1+mish, NHWC) -> conv1
    k_act<CT, 0><<<dim3(NCB1, Bn), 256>>>(x, b1g, b1b, b1m, b1v);
    dim3 gconv(2, 2, Bn);
    k_convtc<CT, NCB1, 0><<<gconv, 256, SMEMSZ>>>(bgg, bgb, bgm, bgv, nullptr, nullptr);

    k_gpool<<<Bn, 256>>>(wlin);

    // act2 (reg+gpo, bn2+mish, NHWC; g_reg referenced in device code) -> conv2
    k_act<CR, 1><<<dim3(NCB2, Bn), 256>>>(nullptr, b2g, b2b, b2m, b2v);
    k_convtc<CR, NCB2, 1><<<gconv, 256, SMEMSZ>>>(nullptr, nullptr, nullptr, nullptr, x, out);
}